// round 16
// baseline (speedup 1.0000x reference)
#include <cuda_runtime.h>
#include <math.h>

#define NB 64
#define NP 16800
#define NO 64
#define GRPS 6
#define PRB (256*GRPS)          // 1536 priors per kABC block
#define NCHA 11                 // ceil(NP/PRB)
#define THRESH 0.35f
#define NEGPOS 7
#define KE_THREADS 1024
#define KE_SMEM (NP*4)

// ---------------- static device scratch (zero-init at load; restored each replay) ----------------
__device__ int2 g_bt[(size_t)NB*NP];           // x = bto bits, y = bti (pre-scatter; scatter patches)
__device__ unsigned g_lcu[(size_t)NB*NP];      // fmap'd ce per (b,p)
__device__ unsigned char g_posm[(size_t)NB*NP];
__device__ unsigned long long g_bpkey[NB*NO];  // reset by kABC epilogue (atomicExch)
__device__ int4 g_win[NB*NO];                  // scatter records (w=-1 => no win); fully rewritten each replay
__device__ float g_part_l[NB], g_part_lm[NB], g_lossc_b[NB];
__device__ int   g_numpos[NB], g_np1_b[NB];    // reset by kEF epilogue
__device__ int   g_ctrA, g_ctrE;               // reset by last blocks

__device__ __forceinline__ float sl1(float x){
    float a = fabsf(x);
    return (a < 1.f) ? 0.5f*a*a : a - 0.5f;
}
__device__ __forceinline__ unsigned fmap(float f){
    unsigned u = __float_as_uint(f);
    return (u & 0x80000000u) ? ~u : (u | 0x80000000u);
}
__device__ __forceinline__ float funmap(unsigned u){
    return __uint_as_float((u & 0x80000000u) ? (u ^ 0x80000000u) : ~u);
}
// warp-aggregated smem histogram add (mask = participating lanes)
__device__ __forceinline__ void hadd(int* hist, unsigned bin, unsigned mask){
    unsigned peers = __match_any_sync(mask, bin);
    if ((__ffs(peers)-1) == (int)(threadIdx.x & 31))
        atomicAdd(&hist[bin], __popc(peers));
}

// full per-prior loss evaluation (shared by kABC tail and kFix)
__device__ __forceinline__ void evalLoss(
    int b, int p, float bto, int t,
    const float* __restrict__ loc, const float* __restrict__ conf,
    const float* __restrict__ landm, const float* __restrict__ priors,
    const float* __restrict__ tr,              // targets row t (15 floats)
    float& lc, int& pos, int& pos1, float& ll, float& llm)
{
    size_t ip = (size_t)b*NP + p;
    float label = tr[14];
    float cf = (bto < THRESH) ? 0.f : label;
    pos  = (cf != 0.f);
    pos1 = (cf > 0.f);
    float2 c = ((const float2*)conf)[ip];
    float d = pos ? (c.x - c.y) : (c.y - c.x);
    lc = fmaxf(d, 0.f) + __logf(1.f + __expf(-fabsf(d)));
    ll = 0.f; llm = 0.f;
    if (pos){
        float4 pr = ((const float4*)priors)[p];
        float pcx=pr.x, pcy=pr.y, pw=pr.z, ph=pr.w;
        float x1=tr[0], y1=tr[1], x2=tr[2], y2=tr[3];
        float iw = __fdividef(1.f, 0.1f*pw);
        float ih = __fdividef(1.f, 0.1f*ph);
        float gcx = ((x1+x2)*0.5f - pcx) * iw;
        float gcy = ((y1+y2)*0.5f - pcy) * ih;
        float gw  = __logf((x2-x1)/pw) * 5.f;
        float gh  = __logf((y2-y1)/ph) * 5.f;
        float4 lr = ((const float4*)loc)[ip];
        ll = sl1(lr.x-gcx) + sl1(lr.y-gcy) + sl1(lr.z-gw) + sl1(lr.w-gh);
        if (pos1){
            const float2* ld2 = (const float2*)(landm + ip*10);
            #pragma unroll
            for (int i=0;i<5;++i){
                float2 lv = ld2[i];
                float gx = (tr[4+2*i] - pcx)*iw;
                float gy = (tr[5+2*i] - pcy)*ih;
                llm += sl1(lv.x-gx) + sl1(lv.y-gy);
            }
        }
    }
}

// ---------------- kernel ABC: IoU argmaxes + fused pre-scatter loss + scatter epilogue ----------------
__global__ void __launch_bounds__(256) kABC(const float* __restrict__ targets,
                                            const float* __restrict__ priors,
                                            const float* __restrict__ loc,
                                            const float* __restrict__ conf,
                                            const float* __restrict__ landm){
    int b   = blockIdx.y;
    int tid = threadIdx.x;
    int blkbase = blockIdx.x*PRB;
    bool am_p0 = (blkbase + tid) == 0;   // global prior 0 (argmax-of-zeros fallback)

    __shared__ float st[NO*15];
    __shared__ float4 sbox[NO];
    __shared__ float  sarea[NO];
    for (int i=tid; i<NO*15; i+=256) st[i] = targets[(size_t)b*NO*15 + i];
    __syncthreads();
    if (tid < NO){
        const float* tr = st + tid*15;
        float x1=tr[0], y1=tr[1], x2=tr[2], y2=tr[3];
        sbox[tid] = make_float4(x1,y1,x2,y2);
        sarea[tid] = (x2-x1)*(y2-y1);
    }
    __syncthreads();

    float x1c[GRPS], y1c[GRPS], x2c[GRPS], y2c[GRPS], pa[GRPS];
    #pragma unroll
    for (int g=0; g<GRPS; ++g){
        int p = blkbase + g*256 + tid;
        int pc = (p < NP) ? p : NP-1;          // clamp tail -> duplicate of last prior
        float4 pr = ((const float4*)priors)[pc];
        x1c[g] = pr.x - pr.z*0.5f; y1c[g] = pr.y - pr.w*0.5f;
        x2c[g] = pr.x + pr.z*0.5f; y2c[g] = pr.y + pr.w*0.5f;
        pa[g]  = (x2c[g]-x1c[g])*(y2c[g]-y1c[g]);
    }

    unsigned ubest[GRPS]; int bt[GRPS];
    #pragma unroll
    for (int g=0; g<GRPS; ++g){ ubest[g]=0u; bt[g]=0; }
    unsigned long long* keyrow = g_bpkey + b*NO;

    for (int t = 0; t < NO; ++t){
        float4 tb = sbox[t];
        float  ta = sarea[t];
        unsigned u[GRPS];
        #pragma unroll
        for (int g=0; g<GRPS; ++g){
            float w = fmaxf(fminf(tb.z, x2c[g]) - fmaxf(tb.x, x1c[g]), 0.f);
            float h = fmaxf(fminf(tb.w, y2c[g]) - fmaxf(tb.y, y1c[g]), 0.f);
            float inter = w*h;
            float v = __fdividef(inter, (ta + pa[g]) - inter);   // v in [0,1]
            u[g] = __float_as_uint(v);
            if (u[g] > ubest[g]){ ubest[g] = u[g]; bt[g] = t; }  // strict >: first t wins
        }
        unsigned lmax = u[0];
        #pragma unroll
        for (int g=1; g<GRPS; ++g) lmax = (u[g] > lmax) ? u[g] : lmax;
        unsigned um = __reduce_max_sync(0xffffffffu, lmax);
        // winner lanes recover their group inside the predicated path;
        // packed atomicMax key resolves value-then-smallest-p ties EXACTLY.
        // um==0 row handled by global prior 0 (argmax of zeros = 0).
        if (lmax == um && (um != 0u || am_p0)){
            int gsel = GRPS-1;
            #pragma unroll
            for (int g=GRPS-2; g>=0; --g) if (u[g] == lmax) gsel = g;   // smallest g
            int cand = blkbase + (gsel<<8) + tid;
            if (cand > NP-1) cand = NP-1;
            unsigned long long key = ((unsigned long long)um << 32) | (unsigned)(~cand);
            atomicMax(&keyrow[t], key);
        }
    }
    #pragma unroll
    for (int g=0; g<GRPS; ++g){
        int p = blkbase + g*256 + tid;
        if (p < NP)
            g_bt[(size_t)b*NP + p] = make_int2((int)ubest[g], bt[g]);
    }

    // -------- fused loss tail (pre-scatter values; kFix patches scattered priors) --------
    {
        float ll=0.f, llm=0.f; int cnt=0;       // cnt = npos | (np1<<16)
        #pragma unroll
        for (int g=0; g<GRPS; ++g){
            int p = blkbase + g*256 + tid;
            if (p < NP){
                float lc; int pos, pos1; float l1, lm1;
                evalLoss(b, p, __uint_as_float(ubest[g]), bt[g],
                         loc, conf, landm, priors, st + bt[g]*15,
                         lc, pos, pos1, l1, lm1);
                size_t ip = (size_t)b*NP + p;
                g_lcu[ip]  = fmap(lc);
                g_posm[ip] = (unsigned char)pos;
                ll += l1; llm += lm1; cnt += pos + (pos1<<16);
            }
        }
        #pragma unroll
        for (int o=16;o>0;o>>=1){
            ll  += __shfl_xor_sync(0xffffffffu, ll,  o);
            llm += __shfl_xor_sync(0xffffffffu, llm, o);
            cnt += __shfl_xor_sync(0xffffffffu, cnt, o);
        }
        __shared__ float sll[8], sllm[8];
        __shared__ int   scnt[8];
        int w = tid >> 5;
        if ((tid & 31) == 0){ sll[w]=ll; sllm[w]=llm; scnt[w]=cnt; }
        __syncthreads();
        if (tid == 0){
            float a=0.f, m=0.f; int cc=0;
            #pragma unroll
            for (int i=0;i<8;++i){ a+=sll[i]; m+=sllm[i]; cc+=scnt[i]; }
            atomicAdd(&g_part_l[b],  a);
            atomicAdd(&g_part_lm[b], m);
            atomicAdd(&g_numpos[b], cc & 0xFFFF);
            atomicAdd(&g_np1_b[b], cc >> 16);
        }
    }

    // -------- fused scatter epilogue: last block, last-writer-wins per row --------
    __threadfence();
    __shared__ int s_last;
    if (tid == 0) s_last = (atomicAdd(&g_ctrA, 1) == NCHA*NB - 1);
    __syncthreads();
    if (s_last){
        if (tid == 0) g_ctrA = 0;
        __shared__ int sp[256];
        int sub = tid >> 6, j = tid & 63;      // 4 rows per iteration
        for (int bb0 = 0; bb0 < NB; bb0 += 4){
            int bb = bb0 + sub;
            unsigned long long key = atomicExch(&g_bpkey[bb*NO + j], 0ull);  // read + reset
            int pidx = (int)(~(unsigned)key);
            sp[tid] = pidx;
            __syncthreads();
            bool win = true;
            for (int j2 = j+1; j2 < 64; ++j2)
                if (sp[(sub<<6) + j2] == pidx) win = false;
            int4 rec = make_int4(0,0,0,-1);
            if (win){
                size_t ip = (size_t)bb*NP + pidx;
                float bpo = __uint_as_float((unsigned)(key >> 32));
                int2 cur = g_bt[ip];
                rec = make_int4(pidx, cur.x, cur.y, (int)(unsigned)(key >> 32));
                g_bt[ip] = make_int2(bpo >= 0.2f ? __float_as_int(2.0f) : cur.x, j);
            }
            g_win[bb*NO + j] = rec;
            __syncthreads();
        }
    }
}

// ---------------- kernel Fix: patch scattered priors' loss contributions ----------------
__global__ void kFix(const float* __restrict__ loc, const float* __restrict__ conf,
                     const float* __restrict__ landm, const float* __restrict__ priors,
                     const float* __restrict__ targets){
    int i = blockIdx.x*256 + threadIdx.x;
    if (i >= NB*NO) return;
    int4 rec = g_win[i];
    if (rec.w == -1) return;
    int b = i >> 6, j = i & 63;
    int pidx = rec.x;
    float bto_o = __int_as_float(rec.y);
    int   t_o   = rec.z;
    float bpo   = __uint_as_float((unsigned)rec.w);
    float bto_n = (bpo >= 0.2f) ? 2.0f : bto_o;

    float lc_o, lc_n, ll_o, ll_n, lm_o, lm_n;
    int po, p1o, pn, p1n;
    evalLoss(b, pidx, bto_o, t_o, loc, conf, landm, priors,
             targets + ((size_t)b*NO + t_o)*15, lc_o, po, p1o, ll_o, lm_o);
    evalLoss(b, pidx, bto_n, j,   loc, conf, landm, priors,
             targets + ((size_t)b*NO + j)*15,   lc_n, pn, p1n, ll_n, lm_n);

    size_t ip = (size_t)b*NP + pidx;
    g_lcu[ip]  = fmap(lc_n);
    g_posm[ip] = (unsigned char)pn;
    if (ll_n != ll_o) atomicAdd(&g_part_l[b],  ll_n - ll_o);
    if (lm_n != lm_o) atomicAdd(&g_part_lm[b], lm_n - lm_o);
    if (pn  != po ) atomicAdd(&g_numpos[b], pn - po);
    if (p1n != p1o) atomicAdd(&g_np1_b[b], p1n - p1o);
}

// ---------------- kernel EF: smem radix top-K (match_any histograms) + fused final reduction ----------------
__global__ void __launch_bounds__(KE_THREADS) kEF(float* __restrict__ out, int out_size){
    extern __shared__ unsigned s_u[];          // NP fmap'd values
    int b = blockIdx.x, tid = threadIdx.x;
    int lane = tid & 31, wid = tid >> 5;
    __shared__ int hist[256];
    __shared__ unsigned s_prefix, s_pmask;
    __shared__ int s_k, s_cgt;
    __shared__ int wsum[32];
    __shared__ float fred[32];
    __shared__ int s_last;
    int npos = g_numpos[b];
    int K = NEGPOS*npos; if (K > NP-1) K = NP-1;
    const unsigned* lcrow = g_lcu + (size_t)b*NP;
    if (tid==0){ s_prefix=0u; s_pmask=0u; s_k=K; s_cgt=0; }
    if (tid < 256) hist[tid]=0;
    __syncthreads();
    // pass 1 (level 3): global -> smem cache + aggregated histogram
    for (int i=tid; i<NP; i+=KE_THREADS){       // warp-uniform bound (NP%32==0)
        unsigned u = lcrow[i];
        s_u[i] = u;
        hadd(hist, u >> 24, 0xffffffffu);
    }
    __syncthreads();
    if (K > 0){
        for (int level=3; level>=0; --level){
            if (wid == 0){
                int k = s_k;
                int h[8]; int lsum = 0;
                #pragma unroll
                for (int i=0;i<8;++i){ h[i] = hist[lane*8+i]; lsum += h[i]; }
                int S = lsum;
                #pragma unroll
                for (int o=1;o<32;o<<=1){
                    int v2 = __shfl_down_sync(0xffffffffu, S, o);
                    if (lane + o < 32) S += v2;
                }
                int above = S - lsum;
                int best = -1, bestSuff = 0;
                int suff = above;
                #pragma unroll
                for (int i=7;i>=0;--i){
                    suff += h[i];
                    if (best < 0 && suff >= k){ best = lane*8 + i; bestSuff = suff; }
                }
                int m = __reduce_max_sync(0xffffffffu, best);
                if (best == m && m >= 0){
                    int cum = bestSuff - h[m & 7];
                    s_cgt += cum;
                    s_k = k - cum;
                    s_prefix |= ((unsigned)m << (level*8));
                    s_pmask  |= (0xFFu << (level*8));
                }
            }
            __syncthreads();
            if (level == 0) break;
            if (tid < 256) hist[tid]=0;
            __syncthreads();
            unsigned pm=s_pmask, pf=s_prefix;
            int nl = level-1;
            for (int i=tid; i<NP; i+=KE_THREADS){
                unsigned u = s_u[i];
                bool pred = ((u & pm) == pf);
                unsigned m = __ballot_sync(0xffffffffu, pred);
                if (pred) hadd(hist, (u >> (nl*8)) & 0xFF, m);
            }
            __syncthreads();
        }
    }
    unsigned v = s_prefix;
    int extra = K - s_cgt;
    const int chunk = (NP + KE_THREADS - 1)/KE_THREADS;   // 17
    int beg = tid*chunk;
    int end = beg + chunk; if (end > NP) end = NP;
    if (beg > NP) beg = NP;
    int eq = 0;
    if (K > 0) for (int i=beg;i<end;++i) if (s_u[i]==v) eq++;
    int sc = eq;
    #pragma unroll
    for (int o=1;o<32;o<<=1){
        int t2 = __shfl_up_sync(0xffffffffu, sc, o);
        if (lane >= o) sc += t2;
    }
    if (lane == 31) wsum[wid] = sc;
    __syncthreads();
    if (tid == 0){
        int acc = 0;
        #pragma unroll
        for (int i=0;i<32;++i){ int tmp = wsum[i]; wsum[i] = acc; acc += tmp; }
    }
    __syncthreads();
    int run = wsum[wid] + (sc - eq);
    const unsigned char* posrow = g_posm + (size_t)b*NP;
    float s = 0.f;
    for (int i=beg; i<end; ++i){
        unsigned u = s_u[i];
        bool inc = (posrow[i] != 0);
        if (K > 0){
            if (u > v) inc = true;
            else if (u == v){ if (run < extra) inc = true; run++; }
        }
        if (inc) s += funmap(u);
    }
    #pragma unroll
    for (int o=16;o>0;o>>=1) s += __shfl_xor_sync(0xffffffffu, s, o);
    if (lane == 0) fred[wid] = s;
    __syncthreads();
    if (tid == 0){
        float a = 0.f;
        #pragma unroll
        for (int i=0;i<32;++i) a += fred[i];
        g_lossc_b[b] = a;
        __threadfence();
        s_last = (atomicAdd(&g_ctrE, 1) == NB - 1);
    }
    __syncthreads();
    // ---- fused final reduction + state reset (last block) ----
    if (s_last){
        __threadfence();
        if (wid == 0){
            float pl  = g_part_l [lane] + g_part_l [lane+32];
            float pm  = g_part_lm[lane] + g_part_lm[lane+32];
            float lcf = g_lossc_b[lane] + g_lossc_b[lane+32];
            int   np  = g_numpos[lane] + g_numpos[lane+32];
            int   np1 = g_np1_b [lane] + g_np1_b [lane+32];
            #pragma unroll
            for (int o=16;o>0;o>>=1){
                pl  += __shfl_xor_sync(0xffffffffu, pl,  o);
                pm  += __shfl_xor_sync(0xffffffffu, pm,  o);
                lcf += __shfl_xor_sync(0xffffffffu, lcf, o);
                np  += __shfl_xor_sync(0xffffffffu, np,  o);
                np1 += __shfl_xor_sync(0xffffffffu, np1, o);
            }
            if (lane == 0){
                float N  = fmaxf((float)np, 1.f);
                float N1 = fmaxf((float)np1, 1.f);
                g_ctrE = 0;
                if (out_size > 0) out[0] = pl  / N;
                if (out_size > 1) out[1] = lcf / N;
                if (out_size > 2) out[2] = pm  / N1;
            }
        }
        // BARRIER: warp 0 must finish reading the per-row accumulators above
        // before any thread resets them (R6 post-timing race).
        __syncthreads();
        if (tid < NB){
            g_numpos[tid] = 0; g_np1_b[tid] = 0;
            g_part_l[tid] = 0.f; g_part_lm[tid] = 0.f;
        }
    }
}

extern "C" void kernel_launch(void* const* d_in, const int* in_sizes, int n_in,
                              void* d_out, int out_size){
    const float* loc     = (const float*)d_in[0];
    const float* conf    = (const float*)d_in[1];
    const float* landm   = (const float*)d_in[2];
    const float* priors  = (const float*)d_in[3];
    const float* targets = (const float*)d_in[4];
    float* out = (float*)d_out;

    cudaFuncSetAttribute(kEF, cudaFuncAttributeMaxDynamicSharedMemorySize, KE_SMEM);

    kABC<<<dim3(NCHA,NB),256>>>(targets, priors, loc, conf, landm);
    kFix<<<16,256>>>(loc, conf, landm, priors, targets);
    kEF<<<NB,KE_THREADS,KE_SMEM>>>(out, out_size);
}

// round 17
// speedup vs baseline: 1.6595x; 1.6595x over previous
#include <cuda_runtime.h>
#include <math.h>

#define NB 64
#define NP 16800
#define NO 64
#define GRPS 6
#define PRB (256*GRPS)          // 1536 priors per kABC block
#define NCHA 11                 // ceil(NP/PRB)
#define NCH 66                  // ceil(NP/256) kD grid
#define THRESH 0.35f
#define NEGPOS 7
#define KE_THREADS 1024
#define KE_SMEM (NP*4)

// ---------------- static device scratch (zero-init at load; restored each replay) ----------------
__device__ int2 g_bt[(size_t)NB*NP];           // x = bto bits, y = bti
__device__ unsigned g_lcu[(size_t)NB*NP];      // fmap'd ce per (b,p)
__device__ unsigned char g_posm[(size_t)NB*NP];
__device__ unsigned long long g_bpkey[NB*NO];  // reset by kABC epilogue (atomicExch)
__device__ float g_part_l[NB], g_part_lm[NB], g_lossc_b[NB];
__device__ int   g_numpos[NB], g_np1_b[NB];    // reset by kEF epilogue
__device__ int   g_ctrA, g_ctrE;               // reset by last blocks

__device__ __forceinline__ float sl1(float x){
    float a = fabsf(x);
    return (a < 1.f) ? 0.5f*a*a : a - 0.5f;
}
__device__ __forceinline__ unsigned fmap(float f){
    unsigned u = __float_as_uint(f);
    return (u & 0x80000000u) ? ~u : (u | 0x80000000u);
}
__device__ __forceinline__ float funmap(unsigned u){
    return __uint_as_float((u & 0x80000000u) ? (u ^ 0x80000000u) : ~u);
}
// warp-aggregated smem histogram add (mask = participating lanes)
__device__ __forceinline__ void hadd(int* hist, unsigned bin, unsigned mask){
    unsigned peers = __match_any_sync(mask, bin);
    if ((__ffs(peers)-1) == (int)(threadIdx.x & 31))
        atomicAdd(&hist[bin], __popc(peers));
}

// ---------------- kernel ABC: IoU argmaxes (6 priors/thread, 4 blocks/SM) + fused scatter ----------------
__global__ void __launch_bounds__(256,4) kABC(const float* __restrict__ targets,
                                              const float* __restrict__ priors){
    int b   = blockIdx.y;
    int tid = threadIdx.x;
    int blkbase = blockIdx.x*PRB;
    bool am_p0 = (blkbase + tid) == 0;   // global prior 0 (argmax-of-zeros fallback)

    __shared__ float4 sbox[NO];
    __shared__ float  sarea[NO];
    if (tid < NO){
        const float* tr = targets + ((size_t)b*NO + tid)*15;
        float x1=tr[0], y1=tr[1], x2=tr[2], y2=tr[3];
        sbox[tid] = make_float4(x1,y1,x2,y2);
        sarea[tid] = (x2-x1)*(y2-y1);
    }
    __syncthreads();

    float x1c[GRPS], y1c[GRPS], x2c[GRPS], y2c[GRPS], pa[GRPS];
    #pragma unroll
    for (int g=0; g<GRPS; ++g){
        int p = blkbase + g*256 + tid;
        int pc = (p < NP) ? p : NP-1;          // clamp tail -> duplicate of last prior
        float4 pr = ((const float4*)priors)[pc];
        x1c[g] = pr.x - pr.z*0.5f; y1c[g] = pr.y - pr.w*0.5f;
        x2c[g] = pr.x + pr.z*0.5f; y2c[g] = pr.y + pr.w*0.5f;
        pa[g]  = (x2c[g]-x1c[g])*(y2c[g]-y1c[g]);
    }

    unsigned ubest[GRPS]; int bt[GRPS];
    #pragma unroll
    for (int g=0; g<GRPS; ++g){ ubest[g]=0u; bt[g]=0; }
    unsigned long long* keyrow = g_bpkey + b*NO;

    for (int t = 0; t < NO; ++t){
        float4 tb = sbox[t];
        float  ta = sarea[t];
        unsigned u[GRPS];
        #pragma unroll
        for (int g=0; g<GRPS; ++g){
            float w = fmaxf(fminf(tb.z, x2c[g]) - fmaxf(tb.x, x1c[g]), 0.f);
            float h = fmaxf(fminf(tb.w, y2c[g]) - fmaxf(tb.y, y1c[g]), 0.f);
            float inter = w*h;
            float sum = ta + pa[g];
            float denom = fmaf(-w, h, sum);                  // sum - w*h, 1 op
            float v = __fdividef(inter, denom);              // v in [0,1]
            u[g] = __float_as_uint(v);
            if (u[g] > ubest[g]){ ubest[g] = u[g]; bt[g] = t; }  // strict >: first t wins
        }
        unsigned lmax = u[0];
        #pragma unroll
        for (int g=1; g<GRPS; ++g) lmax = (u[g] > lmax) ? u[g] : lmax;
        unsigned um = __reduce_max_sync(0xffffffffu, lmax);
        // winner lanes recover their group inside the predicated path;
        // packed atomicMax key resolves value-then-smallest-p ties EXACTLY.
        // um==0 row handled by global prior 0 (argmax of zeros = 0).
        if (lmax == um && (um != 0u || am_p0)){
            int gsel = GRPS-1;
            #pragma unroll
            for (int g=GRPS-2; g>=0; --g) if (u[g] == lmax) gsel = g;   // smallest g
            int cand = blkbase + (gsel<<8) + tid;
            if (cand > NP-1) cand = NP-1;
            unsigned long long key = ((unsigned long long)um << 32) | (unsigned)(~cand);
            atomicMax(&keyrow[t], key);
        }
    }
    #pragma unroll
    for (int g=0; g<GRPS; ++g){
        int p = blkbase + g*256 + tid;
        if (p < NP)
            g_bt[(size_t)b*NP + p] = make_int2((int)ubest[g], bt[g]);
    }

    // -------- fused scatter epilogue: last block, last-writer-wins per row --------
    __threadfence();
    __shared__ int s_last;
    if (tid == 0) s_last = (atomicAdd(&g_ctrA, 1) == NCHA*NB - 1);
    __syncthreads();
    if (s_last){
        if (tid == 0) g_ctrA = 0;
        __shared__ int sp[256];
        int sub = tid >> 6, j = tid & 63;      // 4 rows per iteration
        for (int bb0 = 0; bb0 < NB; bb0 += 4){
            int bb = bb0 + sub;
            unsigned long long key = atomicExch(&g_bpkey[bb*NO + j], 0ull);  // read + reset
            int pidx = (int)(~(unsigned)key);
            sp[tid] = pidx;
            __syncthreads();
            bool win = true;
            for (int j2 = j+1; j2 < 64; ++j2)
                if (sp[(sub<<6) + j2] == pidx) win = false;
            if (win){
                size_t ip = (size_t)bb*NP + pidx;
                float bpo = __uint_as_float((unsigned)(key >> 32));
                int2 cur = g_bt[ip];
                g_bt[ip] = make_int2(bpo >= 0.2f ? __float_as_int(2.0f) : cur.x, j);
            }
            __syncthreads();
        }
    }
}

// ---------------- kernel D: per (b,p) losses (full-chip grid) ----------------
__global__ void kD(const float* __restrict__ loc, const float* __restrict__ conf,
                   const float* __restrict__ landm, const float* __restrict__ priors,
                   const float* __restrict__ targets){
    int b = blockIdx.y;
    int p = blockIdx.x*256 + threadIdx.x;
    int tid = threadIdx.x;
    __shared__ float st[NO*15];
    for (int i=tid; i<NO*15; i+=256) st[i] = targets[(size_t)b*NO*15 + i];
    __syncthreads();
    float ll=0.f, llm=0.f; int cnt=0;     // cnt = cp | (cp1<<16)
    if (p < NP){
        size_t ip = (size_t)b*NP + p;
        int2 btv = g_bt[ip];
        float bto = __int_as_float(btv.x);
        int   t   = btv.y;
        const float* tr = st + t*15;
        float label = tr[14];
        float cf = (bto < THRESH) ? 0.f : label;
        bool pos  = (cf != 0.f);
        bool pos1 = (cf > 0.f);
        float2 c = ((const float2*)conf)[ip];
        float d = pos ? (c.x - c.y) : (c.y - c.x);
        float lc = fmaxf(d, 0.f) + __logf(1.f + __expf(-fabsf(d)));
        g_lcu[ip]  = fmap(lc);
        g_posm[ip] = pos ? 1 : 0;
        if (pos){
            cnt = 1;
            float4 pr = ((const float4*)priors)[p];
            float pcx=pr.x, pcy=pr.y, pw=pr.z, ph=pr.w;
            float x1=tr[0], y1=tr[1], x2=tr[2], y2=tr[3];
            float iw = __fdividef(1.f, 0.1f*pw);
            float ih = __fdividef(1.f, 0.1f*ph);
            float gcx = ((x1+x2)*0.5f - pcx) * iw;
            float gcy = ((y1+y2)*0.5f - pcy) * ih;
            float gw  = __logf((x2-x1)/pw) * 5.f;
            float gh  = __logf((y2-y1)/ph) * 5.f;
            float4 lr = ((const float4*)loc)[ip];
            ll = sl1(lr.x-gcx) + sl1(lr.y-gcy) + sl1(lr.z-gw) + sl1(lr.w-gh);
            if (pos1){
                cnt |= (1<<16);
                const float2* ld2 = (const float2*)(landm + ip*10);
                #pragma unroll
                for (int i=0;i<5;++i){
                    float2 lv = ld2[i];
                    float gx = (tr[4+2*i] - pcx)*iw;
                    float gy = (tr[5+2*i] - pcy)*ih;
                    llm += sl1(lv.x-gx) + sl1(lv.y-gy);
                }
            }
        }
    }
    #pragma unroll
    for (int o=16;o>0;o>>=1){
        ll  += __shfl_xor_sync(0xffffffffu, ll,  o);
        llm += __shfl_xor_sync(0xffffffffu, llm, o);
        cnt += __shfl_xor_sync(0xffffffffu, cnt, o);
    }
    __shared__ float sll[8], sllm[8];
    __shared__ int   scnt[8];
    int w = tid >> 5;
    if ((tid & 31) == 0){ sll[w]=ll; sllm[w]=llm; scnt[w]=cnt; }
    __syncthreads();
    if (tid == 0){
        float a=0.f, m=0.f; int cc=0;
        #pragma unroll
        for (int i=0;i<8;++i){ a+=sll[i]; m+=sllm[i]; cc+=scnt[i]; }
        atomicAdd(&g_part_l[b],  a);
        atomicAdd(&g_part_lm[b], m);
        atomicAdd(&g_numpos[b], cc & 0xFFFF);
        atomicAdd(&g_np1_b[b], cc >> 16);
    }
}

// ---------------- kernel EF: smem radix top-K (match_any histograms) + fused final reduction ----------------
__global__ void __launch_bounds__(KE_THREADS) kEF(float* __restrict__ out, int out_size){
    extern __shared__ unsigned s_u[];          // NP fmap'd values
    int b = blockIdx.x, tid = threadIdx.x;
    int lane = tid & 31, wid = tid >> 5;
    __shared__ int hist[256];
    __shared__ unsigned s_prefix, s_pmask;
    __shared__ int s_k, s_cgt;
    __shared__ int wsum[32];
    __shared__ float fred[32];
    __shared__ int s_last;
    int npos = g_numpos[b];
    int K = NEGPOS*npos; if (K > NP-1) K = NP-1;
    const unsigned* lcrow = g_lcu + (size_t)b*NP;
    if (tid==0){ s_prefix=0u; s_pmask=0u; s_k=K; s_cgt=0; }
    if (tid < 256) hist[tid]=0;
    __syncthreads();
    // pass 1 (level 3): global -> smem cache + aggregated histogram
    for (int i=tid; i<NP; i+=KE_THREADS){       // warp-uniform bound (NP%32==0)
        unsigned u = lcrow[i];
        s_u[i] = u;
        hadd(hist, u >> 24, 0xffffffffu);
    }
    __syncthreads();
    if (K > 0){
        for (int level=3; level>=0; --level){
            if (wid == 0){
                int k = s_k;
                int h[8]; int lsum = 0;
                #pragma unroll
                for (int i=0;i<8;++i){ h[i] = hist[lane*8+i]; lsum += h[i]; }
                int S = lsum;
                #pragma unroll
                for (int o=1;o<32;o<<=1){
                    int v2 = __shfl_down_sync(0xffffffffu, S, o);
                    if (lane + o < 32) S += v2;
                }
                int above = S - lsum;
                int best = -1, bestSuff = 0;
                int suff = above;
                #pragma unroll
                for (int i=7;i>=0;--i){
                    suff += h[i];
                    if (best < 0 && suff >= k){ best = lane*8 + i; bestSuff = suff; }
                }
                int m = __reduce_max_sync(0xffffffffu, best);
                if (best == m && m >= 0){
                    int cum = bestSuff - h[m & 7];
                    s_cgt += cum;
                    s_k = k - cum;
                    s_prefix |= ((unsigned)m << (level*8));
                    s_pmask  |= (0xFFu << (level*8));
                }
            }
            __syncthreads();
            if (level == 0) break;
            if (tid < 256) hist[tid]=0;
            __syncthreads();
            unsigned pm=s_pmask, pf=s_prefix;
            int nl = level-1;
            for (int i=tid; i<NP; i+=KE_THREADS){
                unsigned u = s_u[i];
                bool pred = ((u & pm) == pf);
                unsigned m = __ballot_sync(0xffffffffu, pred);
                if (pred) hadd(hist, (u >> (nl*8)) & 0xFF, m);
            }
            __syncthreads();
        }
    }
    unsigned v = s_prefix;
    int extra = K - s_cgt;
    const int chunk = (NP + KE_THREADS - 1)/KE_THREADS;   // 17
    int beg = tid*chunk;
    int end = beg + chunk; if (end > NP) end = NP;
    if (beg > NP) beg = NP;
    int eq = 0;
    if (K > 0) for (int i=beg;i<end;++i) if (s_u[i]==v) eq++;
    int sc = eq;
    #pragma unroll
    for (int o=1;o<32;o<<=1){
        int t2 = __shfl_up_sync(0xffffffffu, sc, o);
        if (lane >= o) sc += t2;
    }
    if (lane == 31) wsum[wid] = sc;
    __syncthreads();
    if (tid == 0){
        int acc = 0;
        #pragma unroll
        for (int i=0;i<32;++i){ int tmp = wsum[i]; wsum[i] = acc; acc += tmp; }
    }
    __syncthreads();
    int run = wsum[wid] + (sc - eq);
    const unsigned char* posrow = g_posm + (size_t)b*NP;
    float s = 0.f;
    for (int i=beg; i<end; ++i){
        unsigned u = s_u[i];
        bool inc = (posrow[i] != 0);
        if (K > 0){
            if (u > v) inc = true;
            else if (u == v){ if (run < extra) inc = true; run++; }
        }
        if (inc) s += funmap(u);
    }
    #pragma unroll
    for (int o=16;o>0;o>>=1) s += __shfl_xor_sync(0xffffffffu, s, o);
    if (lane == 0) fred[wid] = s;
    __syncthreads();
    if (tid == 0){
        float a = 0.f;
        #pragma unroll
        for (int i=0;i<32;++i) a += fred[i];
        g_lossc_b[b] = a;
        __threadfence();
        s_last = (atomicAdd(&g_ctrE, 1) == NB - 1);
    }
    __syncthreads();
    // ---- fused final reduction + state reset (last block) ----
    if (s_last){
        __threadfence();
        if (wid == 0){
            float pl  = g_part_l [lane] + g_part_l [lane+32];
            float pm  = g_part_lm[lane] + g_part_lm[lane+32];
            float lcf = g_lossc_b[lane] + g_lossc_b[lane+32];
            int   np  = g_numpos[lane] + g_numpos[lane+32];
            int   np1 = g_np1_b [lane] + g_np1_b [lane+32];
            #pragma unroll
            for (int o=16;o>0;o>>=1){
                pl  += __shfl_xor_sync(0xffffffffu, pl,  o);
                pm  += __shfl_xor_sync(0xffffffffu, pm,  o);
                lcf += __shfl_xor_sync(0xffffffffu, lcf, o);
                np  += __shfl_xor_sync(0xffffffffu, np,  o);
                np1 += __shfl_xor_sync(0xffffffffu, np1, o);
            }
            if (lane == 0){
                float N  = fmaxf((float)np, 1.f);
                float N1 = fmaxf((float)np1, 1.f);
                g_ctrE = 0;
                if (out_size > 0) out[0] = pl  / N;
                if (out_size > 1) out[1] = lcf / N;
                if (out_size > 2) out[2] = pm  / N1;
            }
        }
        // BARRIER: warp 0 must finish reading the per-row accumulators above
        // before any thread resets them (R6 post-timing race).
        __syncthreads();
        if (tid < NB){
            g_numpos[tid] = 0; g_np1_b[tid] = 0;
            g_part_l[tid] = 0.f; g_part_lm[tid] = 0.f;
        }
    }
}

extern "C" void kernel_launch(void* const* d_in, const int* in_sizes, int n_in,
                              void* d_out, int out_size){
    const float* loc     = (const float*)d_in[0];
    const float* conf    = (const float*)d_in[1];
    const float* landm   = (const float*)d_in[2];
    const float* priors  = (const float*)d_in[3];
    const float* targets = (const float*)d_in[4];
    float* out = (float*)d_out;

    cudaFuncSetAttribute(kEF, cudaFuncAttributeMaxDynamicSharedMemorySize, KE_SMEM);

    kABC<<<dim3(NCHA,NB),256>>>(targets, priors);
    kD<<<dim3(NCH,NB),256>>>(loc, conf, landm, priors, targets);
    kEF<<<NB,KE_THREADS,KE_SMEM>>>(out, out_size);
}